// round 1
// baseline (speedup 1.0000x reference)
#include <cuda_runtime.h>
#include <cstdint>

// Problem constants (fixed by the reference)
#define Vn 100000
#define Tn 2
#define Nn 32
#define Fn 64
#define Mn 1600000

// inv_degree scratch: [T][V], 800 KB device global (no allocation allowed)
__device__ float g_invdeg[Tn * Vn];

// One thread per (v, t): adjacency is [B=1, V, T, N] row-major, so the 32
// entries for (v,t) are contiguous (128 B). Count entries >= 0, clamp to 1,
// store reciprocal.
__global__ void degree_kernel(const int* __restrict__ adj) {
    int i = blockIdx.x * blockDim.x + threadIdx.x;   // i = v*T + t
    if (i >= Vn * Tn) return;
    const int4* p = reinterpret_cast<const int4*>(adj) + (size_t)i * (Nn / 4);
    int cnt = 0;
#pragma unroll
    for (int k = 0; k < Nn / 4; k++) {
        int4 a = p[k];
        cnt += (a.x >= 0) + (a.y >= 0) + (a.z >= 0) + (a.w >= 0);
    }
    if (cnt < 1) cnt = 1;
    int v = i / Tn;
    int t = i - v * Tn;
    g_invdeg[t * Vn + v] = 1.0f / (float)cnt;
}

// One thread per (row m, float4 chunk j in 0..15). Scale-before-scatter:
// out[v] += features[m] * inv_degree[v], via 16-byte vector RED to L2.
__global__ void scatter_kernel(const int* __restrict__ idx,
                               const float4* __restrict__ feat,
                               float* __restrict__ out,
                               int t) {
    long long g = (long long)blockIdx.x * blockDim.x + threadIdx.x;
    if (g >= (long long)Mn * (Fn / 4)) return;
    int m = (int)(g >> 4);           // row
    int j = (int)(g & 15);           // float4 chunk within row
    int v = __ldg(&idx[m * 3 + 1]);  // b is always 0
    float s = __ldg(&g_invdeg[t * Vn + v]);
    float4 f = feat[(size_t)m * (Fn / 4) + j];
    f.x *= s; f.y *= s; f.z *= s; f.w *= s;
    float* dst = out + (size_t)v * Fn + j * 4;
    asm volatile("red.global.add.v4.f32 [%0], {%1, %2, %3, %4};"
                 :: "l"(dst), "f"(f.x), "f"(f.y), "f"(f.z), "f"(f.w)
                 : "memory");
}

extern "C" void kernel_launch(void* const* d_in, const int* in_sizes, int n_in,
                              void* d_out, int out_size) {
    const int*   adj  = (const int*)  d_in[0];   // [1, V, T, N] int32
    const int*   idx0 = (const int*)  d_in[1];   // [M, 3] int32
    const float* f0   = (const float*)d_in[2];   // [M, F] f32
    const int*   idx1 = (const int*)  d_in[3];
    const float* f1   = (const float*)d_in[4];
    float* out = (float*)d_out;                  // (out0, out1) concatenated: 2*V*F

    // Output is poisoned; zero it (memset node is graph-capturable).
    cudaMemsetAsync(d_out, 0, (size_t)out_size * sizeof(float), 0);

    // inv_degree for both t
    degree_kernel<<<(Vn * Tn + 255) / 256, 256>>>(adj);

    long long total = (long long)Mn * (Fn / 4);
    int blocks = (int)((total + 255) / 256);
    scatter_kernel<<<blocks, 256>>>(idx0, (const float4*)f0, out, 0);
    scatter_kernel<<<blocks, 256>>>(idx1, (const float4*)f1, out + (size_t)Vn * Fn, 1);
}

// round 2
// speedup vs baseline: 1.1746x; 1.1746x over previous
#include <cuda_runtime.h>
#include <cstdint>

// Problem constants (fixed by the reference)
#define Vn 100000
#define Tn 2
#define Nn 32
#define Fn 64
#define Mn 1600000
#define CAP 64   // per-vertex row-list capacity; Poisson(16) tail @64 ~ 1e-19

// Device scratch (load-time allocation — no runtime allocs)
__device__ float g_invdeg[Tn * Vn];          // 800 KB
__device__ int   g_cnt[Tn][Vn];              // 800 KB
__device__ int   g_ridx[Tn][Vn * CAP];       // 51.2 MB

// ---------------------------------------------------------------------------
// Zero the counters (tiny)
__global__ void zero_cnt_kernel() {
    int i = blockIdx.x * blockDim.x + threadIdx.x;
    if (i < Tn * Vn) ((int*)g_cnt)[i] = 0;
}

// ---------------------------------------------------------------------------
// Degree: one int4 per thread, fully coalesced; 8-lane shfl reduce per (v,t).
// adjacency layout [1, V, T, N] → group index gi = v*T + t owns 8 int4s.
__global__ void degree_kernel(const int4* __restrict__ adj) {
    int i = blockIdx.x * blockDim.x + threadIdx.x;       // int4 index
    if (i >= Vn * Tn * (Nn / 4)) return;
    int4 a = adj[i];
    int cnt = (a.x >= 0) + (a.y >= 0) + (a.z >= 0) + (a.w >= 0);
#pragma unroll
    for (int off = 4; off >= 1; off >>= 1)
        cnt += __shfl_down_sync(0xffffffffu, cnt, off, 8);
    if ((threadIdx.x & 7) == 0) {
        int gi = i >> 3;                                  // = v*Tn + t
        int v = gi >> 1, t = gi & 1;
        if (cnt < 1) cnt = 1;
        g_invdeg[t * Vn + v] = 1.0f / (float)cnt;
    }
}

// ---------------------------------------------------------------------------
// Build: one thread per row. Record row id in the vertex bucket; on the
// (astronomically rare) overflow, fall back to a scaled vector RED so the
// kernel stays correct for ANY input distribution.
__global__ void build_kernel(const int* __restrict__ idx,
                             const float4* __restrict__ feat,
                             float* __restrict__ out,
                             const float* __restrict__ invdeg,
                             int* __restrict__ cnt,
                             int* __restrict__ ridx) {
    int m = blockIdx.x * blockDim.x + threadIdx.x;
    if (m >= Mn) return;
    int v = __ldg(&idx[m * 3 + 1]);                      // b is always 0
    int slot = atomicAdd(&cnt[v], 1);
    if (slot < CAP) {
        ridx[v * CAP + slot] = m;
    } else {
        // fallback: scatter this row directly (scaled), gather adds on top
        float s = __ldg(&invdeg[v]);
        const float4* fr = feat + (size_t)m * (Fn / 4);
        float* dst = out + (size_t)v * Fn;
#pragma unroll
        for (int j = 0; j < Fn / 4; j++) {
            float4 f = fr[j];
            asm volatile("red.global.add.v4.f32 [%0], {%1, %2, %3, %4};"
                         :: "l"(dst + j * 4),
                            "f"(f.x * s), "f"(f.y * s), "f"(f.z * s), "f"(f.w * s)
                         : "memory");
        }
    }
}

// ---------------------------------------------------------------------------
// Gather: 16 threads per vertex, one float4 lane each. Register-accumulate
// the vertex's rows, scale once, single RMW-free update of the output.
__global__ void gather_kernel(const int* __restrict__ ridx,
                              const int* __restrict__ cnt,
                              const float4* __restrict__ feat,
                              const float* __restrict__ invdeg,
                              float4* __restrict__ out) {
    int g = blockIdx.x * blockDim.x + threadIdx.x;
    if (g >= Vn * (Fn / 4)) return;
    int v = g >> 4;
    int j = g & 15;
    int c = __ldg(&cnt[v]);
    if (c > CAP) c = CAP;
    const int* rp = ridx + v * CAP;

    float4 acc = make_float4(0.f, 0.f, 0.f, 0.f);
    int i = 0;
    for (; i + 4 <= c; i += 4) {                         // unroll x4 for MLP
        int m0 = __ldg(&rp[i + 0]);
        int m1 = __ldg(&rp[i + 1]);
        int m2 = __ldg(&rp[i + 2]);
        int m3 = __ldg(&rp[i + 3]);
        float4 a0 = feat[(size_t)m0 * 16 + j];
        float4 a1 = feat[(size_t)m1 * 16 + j];
        float4 a2 = feat[(size_t)m2 * 16 + j];
        float4 a3 = feat[(size_t)m3 * 16 + j];
        acc.x += a0.x + a1.x + a2.x + a3.x;
        acc.y += a0.y + a1.y + a2.y + a3.y;
        acc.z += a0.z + a1.z + a2.z + a3.z;
        acc.w += a0.w + a1.w + a2.w + a3.w;
    }
    for (; i < c; i++) {
        int m = __ldg(&rp[i]);
        float4 a = feat[(size_t)m * 16 + j];
        acc.x += a.x; acc.y += a.y; acc.z += a.z; acc.w += a.w;
    }
    float s = __ldg(&invdeg[v]);
    float4 o = out[(size_t)v * 16 + j];                  // holds fallback REDs (usually 0)
    o.x += acc.x * s; o.y += acc.y * s;
    o.z += acc.z * s; o.w += acc.w * s;
    out[(size_t)v * 16 + j] = o;
}

// ---------------------------------------------------------------------------
extern "C" void kernel_launch(void* const* d_in, const int* in_sizes, int n_in,
                              void* d_out, int out_size) {
    const int*   adj  = (const int*)  d_in[0];   // [1, V, T, N] int32
    const int*   idx0 = (const int*)  d_in[1];   // [M, 3] int32
    const float* f0   = (const float*)d_in[2];   // [M, F] f32
    const int*   idx1 = (const int*)  d_in[3];
    const float* f1   = (const float*)d_in[4];
    float* out = (float*)d_out;                  // out0 ++ out1, each [V, F]

    float* out0 = out;
    float* out1 = out + (size_t)Vn * Fn;

    // Resolve device-global scratch addresses (host-side queries, capture-safe)
    float* invdeg; cudaGetSymbolAddress((void**)&invdeg, g_invdeg);
    int*   cnt;    cudaGetSymbolAddress((void**)&cnt,    g_cnt);
    int*   ridx;   cudaGetSymbolAddress((void**)&ridx,   g_ridx);

    cudaMemsetAsync(d_out, 0, (size_t)out_size * sizeof(float), 0);
    zero_cnt_kernel<<<(Tn * Vn + 255) / 256, 256>>>();

    degree_kernel<<<(Vn * Tn * (Nn / 4) + 255) / 256, 256>>>((const int4*)adj);

    build_kernel<<<(Mn + 255) / 256, 256>>>(idx0, (const float4*)f0, out0,
                                            invdeg + 0 * Vn, cnt + 0 * Vn,
                                            ridx + 0 * Vn * CAP);
    build_kernel<<<(Mn + 255) / 256, 256>>>(idx1, (const float4*)f1, out1,
                                            invdeg + 1 * Vn, cnt + 1 * Vn,
                                            ridx + 1 * Vn * CAP);

    int gthreads = Vn * (Fn / 4);
    gather_kernel<<<(gthreads + 255) / 256, 256>>>(ridx + 0 * Vn * CAP,
                                                   cnt + 0 * Vn,
                                                   (const float4*)f0,
                                                   invdeg + 0 * Vn,
                                                   (float4*)out0);
    gather_kernel<<<(gthreads + 255) / 256, 256>>>(ridx + 1 * Vn * CAP,
                                                   cnt + 1 * Vn,
                                                   (const float4*)f1,
                                                   invdeg + 1 * Vn,
                                                   (float4*)out1);
}

// round 3
// speedup vs baseline: 1.3023x; 1.1087x over previous
#include <cuda_runtime.h>
#include <cstdint>

// Problem constants (fixed by the reference)
#define Vn 100000
#define Tn 2
#define Nn 32
#define Fn 64
#define Mn 1600000
#define CAP 64   // per-vertex row-list capacity; Poisson(16) tail @64 ~ 1e-19

// Device scratch (link-time allocation — legal under the no-alloc rule)
__device__ float g_invdeg[Tn * Vn];          // 800 KB
__device__ int   g_cnt[Tn * Vn];             // 800 KB
__device__ int   g_ridx[Tn][Vn * CAP];       // 51.2 MB
__device__ int   g_ovf_cnt[Tn];
__device__ int   g_ovf[Tn][Mn];              // 12.8 MB (full-correctness bound)

// ---------------------------------------------------------------------------
// Degree + counter zeroing. One int4 per thread, coalesced; 8-lane shfl
// reduce per (v,t) group. Also zeroes g_cnt / g_ovf_cnt for this run.
__global__ void degree_kernel(const int4* __restrict__ adj) {
    int i = blockIdx.x * blockDim.x + threadIdx.x;       // int4 index
    if (i < Tn) g_ovf_cnt[i] = 0;
    if (i < Tn * Vn) g_cnt[i] = 0;
    if (i >= Vn * Tn * (Nn / 4)) return;
    int4 a = adj[i];
    int cnt = (a.x >= 0) + (a.y >= 0) + (a.z >= 0) + (a.w >= 0);
#pragma unroll
    for (int off = 4; off >= 1; off >>= 1)
        cnt += __shfl_down_sync(0xffffffffu, cnt, off, 8);
    if ((threadIdx.x & 7) == 0) {
        int gi = i >> 3;                                  // = v*Tn + t
        int v = gi >> 1, t = gi & 1;
        if (cnt < 1) cnt = 1;
        g_invdeg[t * Vn + v] = 1.0f / (float)cnt;
    }
}

// ---------------------------------------------------------------------------
// Build (both t): one thread per row. Bucket the row id; overflow rows go to
// the overflow list (handled by fixup_kernel after gather).
__global__ void build_all(const int* __restrict__ idx0,
                          const int* __restrict__ idx1) {
    int r = blockIdx.x * blockDim.x + threadIdx.x;
    if (r >= Tn * Mn) return;
    int t = (r >= Mn);
    int m = r - t * Mn;
    const int* idx = t ? idx1 : idx0;
    int v = __ldg(&idx[m * 3 + 1]);                      // b is always 0
    int slot = atomicAdd(&g_cnt[t * Vn + v], 1);
    if (slot < CAP) {
        g_ridx[t][v * CAP + slot] = m;
    } else {
        int p = atomicAdd(&g_ovf_cnt[t], 1);
        g_ovf[t][p] = m;
    }
}

// ---------------------------------------------------------------------------
// Gather (both t): one warp per vertex. Row list preloaded into registers
// (2 coalesced LDG), indices distributed via shfl. Lane halves own alternate
// rows -> 2 coalesced 256B feature loads per step, 8 in flight unrolled.
// Warp-uniform trip counts keep every shfl full-warp.
__global__ void gather_all(const float4* __restrict__ f0,
                           const float4* __restrict__ f1,
                           float4* __restrict__ out) {
    int gw = (blockIdx.x * blockDim.x + threadIdx.x) >> 5;
    if (gw >= Tn * Vn) return;
    int t = (gw >= Vn);
    int v = gw - t * Vn;
    int lane = threadIdx.x & 31;
    int half = lane >> 4;                                // which row-parity this lane serves
    int j = lane & 15;                                   // float4 chunk of F=64

    const float4* feat = t ? f1 : f0;
    const int* rp = &g_ridx[t][v * CAP];
    int c = g_cnt[t * Vn + v];
    if (c > CAP) c = CAP;

    // Preload the full row list (entries beyond c are stale-but-in-bounds)
    int r0 = rp[lane];                                   // entries 0..31
    int r1 = rp[32 + lane];                              // entries 32..63

    float4 acc = make_float4(0.f, 0.f, 0.f, 0.f);

    // entry e is served by source lane (e&31), choosing r0/r1 by its own e
    // (halves' e differ by 1 and bases are even, so the r0/r1 predicate is
    //  always consistent between requester and source lane)
    int base = 0;
    for (; base + 7 < c; base += 8) {                    // 8 rows/warp/iter
        int e0 = base + half, e1 = e0 + 2, e2 = e0 + 4, e3 = e0 + 6;
        int m0 = __shfl_sync(0xffffffffu, e0 < 32 ? r0 : r1, e0 & 31);
        int m1 = __shfl_sync(0xffffffffu, e1 < 32 ? r0 : r1, e1 & 31);
        int m2 = __shfl_sync(0xffffffffu, e2 < 32 ? r0 : r1, e2 & 31);
        int m3 = __shfl_sync(0xffffffffu, e3 < 32 ? r0 : r1, e3 & 31);
        float4 a0 = feat[(size_t)m0 * 16 + j];
        float4 a1 = feat[(size_t)m1 * 16 + j];
        float4 a2 = feat[(size_t)m2 * 16 + j];
        float4 a3 = feat[(size_t)m3 * 16 + j];
        acc.x += a0.x + a1.x + a2.x + a3.x;
        acc.y += a0.y + a1.y + a2.y + a3.y;
        acc.z += a0.z + a1.z + a2.z + a3.z;
        acc.w += a0.w + a1.w + a2.w + a3.w;
    }
    for (; base < c; base += 2) {                        // warp-uniform remainder
        int e = base + half;
        int m = __shfl_sync(0xffffffffu, e < 32 ? r0 : r1, e & 31);
        if (e < c) {
            float4 a = feat[(size_t)m * 16 + j];
            acc.x += a.x; acc.y += a.y; acc.z += a.z; acc.w += a.w;
        }
    }

    // merge the two halves (lane j gets half-1's partial from lane j+16)
    acc.x += __shfl_xor_sync(0xffffffffu, acc.x, 16);
    acc.y += __shfl_xor_sync(0xffffffffu, acc.y, 16);
    acc.z += __shfl_xor_sync(0xffffffffu, acc.z, 16);
    acc.w += __shfl_xor_sync(0xffffffffu, acc.w, 16);

    if (half == 0) {
        float s = __ldg(&g_invdeg[t * Vn + v]);
        acc.x *= s; acc.y *= s; acc.z *= s; acc.w *= s;
        out[((size_t)(t * Vn + v)) * 16 + j] = acc;      // full-coverage plain store
    }
}

// ---------------------------------------------------------------------------
// Fixup: RED overflow rows (normally zero work) on top of gather's stores.
__global__ void fixup_kernel(const int* __restrict__ idx0,
                             const int* __restrict__ idx1,
                             const float4* __restrict__ f0,
                             const float4* __restrict__ f1,
                             float* __restrict__ out) {
#pragma unroll
    for (int t = 0; t < Tn; t++) {
        int n = g_ovf_cnt[t];
        int total = n * (Fn / 4);
        const int* idx = t ? idx1 : idx0;
        const float4* feat = t ? f1 : f0;
        for (int w = blockIdx.x * blockDim.x + threadIdx.x; w < total;
             w += gridDim.x * blockDim.x) {
            int e = w >> 4, j = w & 15;
            int m = g_ovf[t][e];
            int v = idx[m * 3 + 1];
            float s = g_invdeg[t * Vn + v];
            float4 f = feat[(size_t)m * 16 + j];
            float* dst = out + ((size_t)(t * Vn + v) * 16 + j) * 4;
            asm volatile("red.global.add.v4.f32 [%0], {%1, %2, %3, %4};"
                         :: "l"(dst),
                            "f"(f.x * s), "f"(f.y * s), "f"(f.z * s), "f"(f.w * s)
                         : "memory");
        }
    }
}

// ---------------------------------------------------------------------------
extern "C" void kernel_launch(void* const* d_in, const int* in_sizes, int n_in,
                              void* d_out, int out_size) {
    const int*   adj  = (const int*)  d_in[0];   // [1, V, T, N] int32
    const int*   idx0 = (const int*)  d_in[1];   // [M, 3] int32
    const float* f0   = (const float*)d_in[2];   // [M, F] f32
    const int*   idx1 = (const int*)  d_in[3];
    const float* f1   = (const float*)d_in[4];
    float* out = (float*)d_out;                  // out0 ++ out1, each [V, F]

    degree_kernel<<<(Vn * Tn * (Nn / 4) + 255) / 256, 256>>>((const int4*)adj);

    build_all<<<(Tn * Mn + 255) / 256, 256>>>(idx0, idx1);

    int gwarps = Tn * Vn;                        // one warp per (t, v)
    gather_all<<<(gwarps * 32 + 255) / 256, 256>>>((const float4*)f0,
                                                   (const float4*)f1,
                                                   (float4*)out);

    fixup_kernel<<<296, 256>>>(idx0, idx1, (const float4*)f0,
                               (const float4*)f1, out);
}

// round 4
// speedup vs baseline: 1.3521x; 1.0382x over previous
#include <cuda_runtime.h>
#include <cstdint>

// Problem constants (fixed by the reference)
#define Vn 100000
#define Tn 2
#define Nn 32
#define Fn 64
#define Mn 1600000
#define CAP 32   // per-vertex bucket capacity; overflow -> list + fixup (always correct)

// Device scratch (zero-initialized at module load; re-zeroed each launch)
__device__ float g_invdeg[Tn * Vn];          // 800 KB
__device__ int   g_cnt[Tn * Vn];             // 800 KB
__device__ int   g_ridx[Tn][Vn * CAP];       // 25.6 MB
__device__ int   g_ovf_cnt[Tn];
__device__ int   g_ovf[Tn][Mn];              // 12.8 MB (full-correctness bound)

#define BUILD_BLOCKS ((Tn * Mn + 255) / 256)             // 12500
#define DEG_BLOCKS   ((Vn * Tn * (Nn / 4) + 255) / 256)  // 6250

// ---------------------------------------------------------------------------
// Prep: build (blocks [0, BUILD_BLOCKS)) + degree (rest), fused so degree's
// bandwidth hides under build's atomic latency. Requires g_cnt/g_ovf_cnt == 0
// on entry (true at load; restored by fixup + zero_tail each launch).
__global__ void prep_kernel(const int4* __restrict__ adj,
                            const int* __restrict__ idx0,
                            const int* __restrict__ idx1) {
    if (blockIdx.x < BUILD_BLOCKS) {
        int r = blockIdx.x * blockDim.x + threadIdx.x;
        if (r >= Tn * Mn) return;
        int t = (r >= Mn);
        int m = r - t * Mn;
        const int* idx = t ? idx1 : idx0;
        int v = __ldcs(&idx[m * 3 + 1]);                 // b is always 0
        int slot = atomicAdd(&g_cnt[t * Vn + v], 1);
        if (slot < CAP) {
            g_ridx[t][v * CAP + slot] = m;
        } else {
            int p = atomicAdd(&g_ovf_cnt[t], 1);
            g_ovf[t][p] = m;
        }
    } else {
        int i = (blockIdx.x - BUILD_BLOCKS) * blockDim.x + threadIdx.x;
        if (i >= Vn * Tn * (Nn / 4)) return;
        int4 a = adj[i];
        int cnt = (a.x >= 0) + (a.y >= 0) + (a.z >= 0) + (a.w >= 0);
#pragma unroll
        for (int off = 4; off >= 1; off >>= 1)
            cnt += __shfl_down_sync(0xffffffffu, cnt, off, 8);
        if ((threadIdx.x & 7) == 0) {
            int gi = i >> 3;                              // = v*Tn + t
            int v = gi >> 1, t = gi & 1;
            if (cnt < 1) cnt = 1;
            g_invdeg[t * Vn + v] = 1.0f / (float)cnt;
        }
    }
}

// ---------------------------------------------------------------------------
// Gather (both t): one warp per vertex. Bucket preloaded into one register
// per lane (coalesced LDG), indices distributed via shfl. Lane halves own
// alternate rows; 16-row main iteration keeps 8 LDG.128 in flight per warp.
__global__ void gather_all(const float4* __restrict__ f0,
                           const float4* __restrict__ f1,
                           float4* __restrict__ out) {
    int gw = (blockIdx.x * blockDim.x + threadIdx.x) >> 5;
    if (gw >= Tn * Vn) return;
    int t = (gw >= Vn);
    int v = gw - t * Vn;
    int lane = threadIdx.x & 31;
    int half = lane >> 4;                                // row-parity this lane serves
    int j = lane & 15;                                   // float4 chunk of F=64

    const float4* feat = t ? f1 : f0;
    int c = g_cnt[t * Vn + v];
    if (c > CAP) c = CAP;
    int r0 = g_ridx[t][v * CAP + lane];                  // full bucket in registers

    float4 acc0 = make_float4(0.f, 0.f, 0.f, 0.f);
    float4 acc1 = make_float4(0.f, 0.f, 0.f, 0.f);

    int base = 0;
    for (; base + 15 < c; base += 16) {                  // 16 rows/warp/iter
        int m0 = __shfl_sync(0xffffffffu, r0, (base + half) & 31);
        int m1 = __shfl_sync(0xffffffffu, r0, (base + half + 2) & 31);
        int m2 = __shfl_sync(0xffffffffu, r0, (base + half + 4) & 31);
        int m3 = __shfl_sync(0xffffffffu, r0, (base + half + 6) & 31);
        int m4 = __shfl_sync(0xffffffffu, r0, (base + half + 8) & 31);
        int m5 = __shfl_sync(0xffffffffu, r0, (base + half + 10) & 31);
        int m6 = __shfl_sync(0xffffffffu, r0, (base + half + 12) & 31);
        int m7 = __shfl_sync(0xffffffffu, r0, (base + half + 14) & 31);
        float4 a0 = __ldcs(&feat[(size_t)m0 * 16 + j]);
        float4 a1 = __ldcs(&feat[(size_t)m1 * 16 + j]);
        float4 a2 = __ldcs(&feat[(size_t)m2 * 16 + j]);
        float4 a3 = __ldcs(&feat[(size_t)m3 * 16 + j]);
        float4 a4 = __ldcs(&feat[(size_t)m4 * 16 + j]);
        float4 a5 = __ldcs(&feat[(size_t)m5 * 16 + j]);
        float4 a6 = __ldcs(&feat[(size_t)m6 * 16 + j]);
        float4 a7 = __ldcs(&feat[(size_t)m7 * 16 + j]);
        acc0.x += a0.x + a1.x + a2.x + a3.x;
        acc0.y += a0.y + a1.y + a2.y + a3.y;
        acc0.z += a0.z + a1.z + a2.z + a3.z;
        acc0.w += a0.w + a1.w + a2.w + a3.w;
        acc1.x += a4.x + a5.x + a6.x + a7.x;
        acc1.y += a4.y + a5.y + a6.y + a7.y;
        acc1.z += a4.z + a5.z + a6.z + a7.z;
        acc1.w += a4.w + a5.w + a6.w + a7.w;
    }
    for (; base + 7 < c; base += 8) {                    // 8 rows/warp/iter
        int m0 = __shfl_sync(0xffffffffu, r0, (base + half) & 31);
        int m1 = __shfl_sync(0xffffffffu, r0, (base + half + 2) & 31);
        int m2 = __shfl_sync(0xffffffffu, r0, (base + half + 4) & 31);
        int m3 = __shfl_sync(0xffffffffu, r0, (base + half + 6) & 31);
        float4 a0 = __ldcs(&feat[(size_t)m0 * 16 + j]);
        float4 a1 = __ldcs(&feat[(size_t)m1 * 16 + j]);
        float4 a2 = __ldcs(&feat[(size_t)m2 * 16 + j]);
        float4 a3 = __ldcs(&feat[(size_t)m3 * 16 + j]);
        acc0.x += a0.x + a1.x + a2.x + a3.x;
        acc0.y += a0.y + a1.y + a2.y + a3.y;
        acc0.z += a0.z + a1.z + a2.z + a3.z;
        acc0.w += a0.w + a1.w + a2.w + a3.w;
    }
    for (; base < c; base += 2) {                        // warp-uniform remainder
        int e = base + half;
        int m = __shfl_sync(0xffffffffu, r0, e & 31);
        if (e < c) {
            float4 a = __ldcs(&feat[(size_t)m * 16 + j]);
            acc0.x += a.x; acc0.y += a.y; acc0.z += a.z; acc0.w += a.w;
        }
    }

    acc0.x += acc1.x; acc0.y += acc1.y; acc0.z += acc1.z; acc0.w += acc1.w;
    // merge lane-halves
    acc0.x += __shfl_xor_sync(0xffffffffu, acc0.x, 16);
    acc0.y += __shfl_xor_sync(0xffffffffu, acc0.y, 16);
    acc0.z += __shfl_xor_sync(0xffffffffu, acc0.z, 16);
    acc0.w += __shfl_xor_sync(0xffffffffu, acc0.w, 16);

    if (half == 0) {
        float s = __ldg(&g_invdeg[t * Vn + v]);
        acc0.x *= s; acc0.y *= s; acc0.z *= s; acc0.w *= s;
        out[((size_t)(t * Vn + v)) * 16 + j] = acc0;     // full-coverage plain store
    }
}

// ---------------------------------------------------------------------------
// Fixup: RED overflow rows (normally ~0 work) on top of gather's stores.
// Also re-zeroes g_cnt for the next launch/replay.
__global__ void fixup_kernel(const int* __restrict__ idx0,
                             const int* __restrict__ idx1,
                             const float4* __restrict__ f0,
                             const float4* __restrict__ f1,
                             float* __restrict__ out) {
    int tid = blockIdx.x * blockDim.x + threadIdx.x;
    int nthreads = gridDim.x * blockDim.x;
#pragma unroll
    for (int t = 0; t < Tn; t++) {
        int n = g_ovf_cnt[t];
        int total = n * (Fn / 4);
        const int* idx = t ? idx1 : idx0;
        const float4* feat = t ? f1 : f0;
        for (int w = tid; w < total; w += nthreads) {
            int e = w >> 4, j = w & 15;
            int m = g_ovf[t][e];
            int v = idx[m * 3 + 1];
            float s = g_invdeg[t * Vn + v];
            float4 f = feat[(size_t)m * 16 + j];
            float* dst = out + ((size_t)(t * Vn + v) * 16 + j) * 4;
            asm volatile("red.global.add.v4.f32 [%0], {%1, %2, %3, %4};"
                         :: "l"(dst),
                            "f"(f.x * s), "f"(f.y * s), "f"(f.z * s), "f"(f.w * s)
                         : "memory");
        }
    }
    for (int i = tid; i < Tn * Vn; i += nthreads)        // reset for next launch
        g_cnt[i] = 0;
}

// Trailing nano-kernel: zero the overflow counters AFTER fixup consumed them.
__global__ void zero_tail_kernel() {
    if (threadIdx.x < Tn) g_ovf_cnt[threadIdx.x] = 0;
}

// ---------------------------------------------------------------------------
extern "C" void kernel_launch(void* const* d_in, const int* in_sizes, int n_in,
                              void* d_out, int out_size) {
    const int*   adj  = (const int*)  d_in[0];   // [1, V, T, N] int32
    const int*   idx0 = (const int*)  d_in[1];   // [M, 3] int32
    const float* f0   = (const float*)d_in[2];   // [M, F] f32
    const int*   idx1 = (const int*)  d_in[3];
    const float* f1   = (const float*)d_in[4];
    float* out = (float*)d_out;                  // out0 ++ out1, each [V, F]

    prep_kernel<<<BUILD_BLOCKS + DEG_BLOCKS, 256>>>((const int4*)adj, idx0, idx1);

    int gwarps = Tn * Vn;                        // one warp per (t, v)
    gather_all<<<(gwarps * 32 + 255) / 256, 256>>>((const float4*)f0,
                                                   (const float4*)f1,
                                                   (float4*)out);

    fixup_kernel<<<128, 256>>>(idx0, idx1, (const float4*)f0,
                               (const float4*)f1, out);
    zero_tail_kernel<<<1, 32>>>();
}

// round 5
// speedup vs baseline: 1.4285x; 1.0566x over previous
#include <cuda_runtime.h>
#include <cstdint>

// Problem constants (fixed by the reference)
#define Vn 100000
#define Tn 2
#define Nn 32
#define Fn 64
#define Mn 1600000
#define CAP 32   // bucket capacity; overflow -> list + fixup (correct for any input)

// Device scratch (zero-initialized at module load; restored every launch)
__device__ float g_invdeg[Tn * Vn];          // 800 KB
__device__ int   g_cnt[Tn * Vn];             // 800 KB
__device__ int   g_ridx[Tn][Vn * CAP];       // 25.6 MB
__device__ int   g_ovf_cnt[Tn];
__device__ int   g_ovf[Tn][Mn];              // 12.8 MB (full-correctness bound)
__device__ int   g_done;                     // fixup arrival counter

#define ROWS_PER_THR 4
#define BUILD_BLOCKS ((Mn + 256 * ROWS_PER_THR - 1) / (256 * ROWS_PER_THR))  // 1563
#define DEG_BLOCKS   ((Vn * Tn * (Nn / 4) + 255) / 256)                      // 6250
#define GATHER_BLOCKS (Vn / 8)                                               // 12500

// ---------------------------------------------------------------------------
// Build one t: 4 rows/thread, coalesced int4 index loads. Requires
// g_cnt[t]/g_ovf_cnt[t] == 0 on entry.
__device__ __forceinline__ void build_t(const int* __restrict__ idx, int t,
                                        int blk) {
    int base = (blk * 256 + threadIdx.x) * ROWS_PER_THR;
    if (base >= Mn) return;
    const int4* q = (const int4*)idx + (size_t)base * 3 / 4;   // 3 int4 per 4 rows
    int4 q0 = __ldcs(&q[0]), q1 = __ldcs(&q[1]), q2 = __ldcs(&q[2]);
    int vs[ROWS_PER_THR] = {q0.y, q1.x, q1.w, q2.z};
#pragma unroll
    for (int k = 0; k < ROWS_PER_THR; k++) {
        int m = base + k;
        if (m >= Mn) break;
        int v = vs[k];
        int slot = atomicAdd(&g_cnt[t * Vn + v], 1);
        if (slot < CAP) {
            g_ridx[t][v * CAP + slot] = m;
        } else {
            int p = atomicAdd(&g_ovf_cnt[t], 1);
            g_ovf[t][p] = m;
        }
    }
}

// ---------------------------------------------------------------------------
// Gather one vertex-warp for time t. Bucket in registers, shfl-distributed;
// lane halves own alternate rows; up to 8 LDG.128 in flight per warp.
__device__ __forceinline__ void gather_t(const float4* __restrict__ feat,
                                         float4* __restrict__ out, int t,
                                         int v) {
    int lane = threadIdx.x & 31;
    int half = lane >> 4;
    int j = lane & 15;

    int c = g_cnt[t * Vn + v];
    if (c > CAP) c = CAP;
    int r0 = g_ridx[t][v * CAP + lane];

    float4 acc0 = make_float4(0.f, 0.f, 0.f, 0.f);
    float4 acc1 = make_float4(0.f, 0.f, 0.f, 0.f);

    int base = 0;
    for (; base + 15 < c; base += 16) {
        int m0 = __shfl_sync(0xffffffffu, r0, (base + half) & 31);
        int m1 = __shfl_sync(0xffffffffu, r0, (base + half + 2) & 31);
        int m2 = __shfl_sync(0xffffffffu, r0, (base + half + 4) & 31);
        int m3 = __shfl_sync(0xffffffffu, r0, (base + half + 6) & 31);
        int m4 = __shfl_sync(0xffffffffu, r0, (base + half + 8) & 31);
        int m5 = __shfl_sync(0xffffffffu, r0, (base + half + 10) & 31);
        int m6 = __shfl_sync(0xffffffffu, r0, (base + half + 12) & 31);
        int m7 = __shfl_sync(0xffffffffu, r0, (base + half + 14) & 31);
        float4 a0 = __ldcs(&feat[(size_t)m0 * 16 + j]);
        float4 a1 = __ldcs(&feat[(size_t)m1 * 16 + j]);
        float4 a2 = __ldcs(&feat[(size_t)m2 * 16 + j]);
        float4 a3 = __ldcs(&feat[(size_t)m3 * 16 + j]);
        float4 a4 = __ldcs(&feat[(size_t)m4 * 16 + j]);
        float4 a5 = __ldcs(&feat[(size_t)m5 * 16 + j]);
        float4 a6 = __ldcs(&feat[(size_t)m6 * 16 + j]);
        float4 a7 = __ldcs(&feat[(size_t)m7 * 16 + j]);
        acc0.x += a0.x + a1.x + a2.x + a3.x;
        acc0.y += a0.y + a1.y + a2.y + a3.y;
        acc0.z += a0.z + a1.z + a2.z + a3.z;
        acc0.w += a0.w + a1.w + a2.w + a3.w;
        acc1.x += a4.x + a5.x + a6.x + a7.x;
        acc1.y += a4.y + a5.y + a6.y + a7.y;
        acc1.z += a4.z + a5.z + a6.z + a7.z;
        acc1.w += a4.w + a5.w + a6.w + a7.w;
    }
    for (; base + 7 < c; base += 8) {
        int m0 = __shfl_sync(0xffffffffu, r0, (base + half) & 31);
        int m1 = __shfl_sync(0xffffffffu, r0, (base + half + 2) & 31);
        int m2 = __shfl_sync(0xffffffffu, r0, (base + half + 4) & 31);
        int m3 = __shfl_sync(0xffffffffu, r0, (base + half + 6) & 31);
        float4 a0 = __ldcs(&feat[(size_t)m0 * 16 + j]);
        float4 a1 = __ldcs(&feat[(size_t)m1 * 16 + j]);
        float4 a2 = __ldcs(&feat[(size_t)m2 * 16 + j]);
        float4 a3 = __ldcs(&feat[(size_t)m3 * 16 + j]);
        acc0.x += a0.x + a1.x + a2.x + a3.x;
        acc0.y += a0.y + a1.y + a2.y + a3.y;
        acc0.z += a0.z + a1.z + a2.z + a3.z;
        acc0.w += a0.w + a1.w + a2.w + a3.w;
    }
    for (; base < c; base += 2) {
        int e = base + half;
        int m = __shfl_sync(0xffffffffu, r0, e & 31);
        if (e < c) {
            float4 a = __ldcs(&feat[(size_t)m * 16 + j]);
            acc0.x += a.x; acc0.y += a.y; acc0.z += a.z; acc0.w += a.w;
        }
    }

    acc0.x += acc1.x; acc0.y += acc1.y; acc0.z += acc1.z; acc0.w += acc1.w;
    acc0.x += __shfl_xor_sync(0xffffffffu, acc0.x, 16);
    acc0.y += __shfl_xor_sync(0xffffffffu, acc0.y, 16);
    acc0.z += __shfl_xor_sync(0xffffffffu, acc0.z, 16);
    acc0.w += __shfl_xor_sync(0xffffffffu, acc0.w, 16);

    if (half == 0) {
        float s = __ldg(&g_invdeg[t * Vn + v]);
        acc0.x *= s; acc0.y *= s; acc0.z *= s; acc0.w *= s;
        out[((size_t)(t * Vn + v)) * 16 + j] = acc0;
    }
}

// ---------------------------------------------------------------------------
// K1: build(t=0) blocks [0, BUILD_BLOCKS), degree blocks after.
__global__ void k1_build0_degree(const int* __restrict__ idx0,
                                 const int4* __restrict__ adj) {
    if (blockIdx.x < BUILD_BLOCKS) {
        build_t(idx0, 0, blockIdx.x);
    } else {
        int i = (blockIdx.x - BUILD_BLOCKS) * blockDim.x + threadIdx.x;
        if (i >= Vn * Tn * (Nn / 4)) return;
        int4 a = adj[i];
        int cnt = (a.x >= 0) + (a.y >= 0) + (a.z >= 0) + (a.w >= 0);
#pragma unroll
        for (int off = 4; off >= 1; off >>= 1)
            cnt += __shfl_down_sync(0xffffffffu, cnt, off, 8);
        if ((threadIdx.x & 7) == 0) {
            int gi = i >> 3;                              // = v*Tn + t
            int v = gi >> 1, t = gi & 1;
            if (cnt < 1) cnt = 1;
            g_invdeg[t * Vn + v] = 1.0f / (float)cnt;
        }
    }
}

// ---------------------------------------------------------------------------
// K2: gather(t=0) overlapped with build(t=1). Every 8th block (l==7, while
// build blocks remain) does build; others gather. Build blocks are spread
// through the launch order so they co-reside with gather from wave 1.
__global__ void k2_gather0_build1(const float4* __restrict__ f0,
                                  const int* __restrict__ idx1,
                                  float4* __restrict__ out) {
    int g = blockIdx.x >> 3, l = blockIdx.x & 7;
    if (l == 7 && g < BUILD_BLOCKS) {
        build_t(idx1, 1, g);
    } else {
        int nb = g < BUILD_BLOCKS ? g : BUILD_BLOCKS;    // build blocks before us
        int gid = blockIdx.x - nb;                       // 0 .. GATHER_BLOCKS-1
        int v = gid * 8 + ((int)threadIdx.x >> 5);
        if (v < Vn) gather_t(f0, out, 0, v);
    }
}

// K3: gather(t=1).
__global__ void k3_gather1(const float4* __restrict__ f1,
                           float4* __restrict__ out) {
    int v = blockIdx.x * 8 + ((int)threadIdx.x >> 5);
    if (v < Vn) gather_t(f1, out, 1, v);
}

// ---------------------------------------------------------------------------
// K4: RED overflow rows (normally zero), re-zero g_cnt; the last block to
// finish zeroes the overflow counters for the next launch/replay.
__global__ void k4_fixup(const int* __restrict__ idx0,
                         const int* __restrict__ idx1,
                         const float4* __restrict__ f0,
                         const float4* __restrict__ f1,
                         float* __restrict__ out) {
    int tid = blockIdx.x * blockDim.x + threadIdx.x;
    int nthreads = gridDim.x * blockDim.x;
#pragma unroll
    for (int t = 0; t < Tn; t++) {
        int n = g_ovf_cnt[t];
        int total = n * (Fn / 4);
        const int* idx = t ? idx1 : idx0;
        const float4* feat = t ? f1 : f0;
        for (int w = tid; w < total; w += nthreads) {
            int e = w >> 4, j = w & 15;
            int m = g_ovf[t][e];
            int v = idx[m * 3 + 1];
            float s = g_invdeg[t * Vn + v];
            float4 f = feat[(size_t)m * 16 + j];
            float* dst = out + ((size_t)(t * Vn + v) * 16 + j) * 4;
            asm volatile("red.global.add.v4.f32 [%0], {%1, %2, %3, %4};"
                         :: "l"(dst),
                            "f"(f.x * s), "f"(f.y * s), "f"(f.z * s), "f"(f.w * s)
                         : "memory");
        }
    }
    for (int i = tid; i < Tn * Vn; i += nthreads)        // reset buckets
        g_cnt[i] = 0;

    __syncthreads();
    __threadfence();
    if (threadIdx.x == 0) {                              // last block zeroes ovf
        int old = atomicAdd(&g_done, 1);
        if (old == (int)gridDim.x - 1) {
            g_ovf_cnt[0] = 0;
            g_ovf_cnt[1] = 0;
            g_done = 0;
        }
    }
}

// ---------------------------------------------------------------------------
extern "C" void kernel_launch(void* const* d_in, const int* in_sizes, int n_in,
                              void* d_out, int out_size) {
    const int*   adj  = (const int*)  d_in[0];   // [1, V, T, N] int32
    const int*   idx0 = (const int*)  d_in[1];   // [M, 3] int32
    const float* f0   = (const float*)d_in[2];   // [M, F] f32
    const int*   idx1 = (const int*)  d_in[3];
    const float* f1   = (const float*)d_in[4];
    float* out = (float*)d_out;                  // out0 ++ out1, each [V, F]

    k1_build0_degree<<<BUILD_BLOCKS + DEG_BLOCKS, 256>>>(idx0, (const int4*)adj);

    k2_gather0_build1<<<GATHER_BLOCKS + BUILD_BLOCKS, 256>>>(
        (const float4*)f0, idx1, (float4*)out);

    k3_gather1<<<GATHER_BLOCKS, 256>>>((const float4*)f1, (float4*)out);

    k4_fixup<<<128, 256>>>(idx0, idx1, (const float4*)f0, (const float4*)f1,
                           out);
}